// round 2
// baseline (speedup 1.0000x reference)
#include <cuda_runtime.h>
#include <math.h>

#define Bb   4
#define Nn   4096
#define Dd   512
#define Hh   8
#define DHd  64
#define Mm   266
#define BHh  32          // B*H
#define BNn  16384       // B*N
#define MPAD 268

// -------------------- scratch (static device memory; no allocs) --------------------
__device__ float g_q  [(size_t)BHh * Nn * DHd];
__device__ float g_k  [(size_t)BHh * Nn * DHd];
__device__ float g_v  [(size_t)BHh * Nn * DHd];
__device__ float g_qp [(size_t)BHh * Nn * Mm];
__device__ float g_kp [(size_t)BHh * Nn * Mm];
__device__ float g_attn[(size_t)BNn * Dd];
__device__ float g_ctx [(size_t)BHh * Mm * DHd];
__device__ float g_ksum[(size_t)BHh * Mm];
__device__ float g_kmax[BHh];
__device__ float g_diag[(size_t)BHh * Nn];
__device__ float g_dinv[(size_t)BHh * Nn];

// -------------------- helpers --------------------
__device__ __forceinline__ void atomicMaxF(float* addr, float val) {
    int* ai = (int*)addr;
    int old = *ai;
    while (__int_as_float(old) < val) {
        int assumed = old;
        old = atomicCAS(ai, assumed, __float_as_int(val));
        if (old == assumed) break;
    }
}

// FMA-only exp (avoids MUFU throughput wall). ~1e-7 rel error, args are <= 0 here.
__device__ __forceinline__ float fast_exp(float x) {
    float y = fmaxf(x * 1.4426950408889634f, -126.0f);
    float r = rintf(y);
    float f = y - r;
    float p = 1.5403530e-4f;
    p = fmaf(p, f, 1.3333558e-3f);
    p = fmaf(p, f, 9.6181291e-3f);
    p = fmaf(p, f, 5.5504109e-2f);
    p = fmaf(p, f, 2.4022651e-1f);
    p = fmaf(p, f, 6.9314718e-1f);
    p = fmaf(p, f, 1.0f);
    int e = (int)r;
    float s = __int_as_float((e + 127) << 23);
    return p * s;
}

#define NORMALIZER 0.35355339059327373f   // 64^-0.25
#define RATIO      0.061313934f           // 266^-0.5
#define EPSF       1e-4f

// -------------------- init scratch accumulators --------------------
__global__ void k_init() {
    int i = blockIdx.x * 256 + threadIdx.x;
    if (i < BHh * Mm * DHd) g_ctx[i]  = 0.0f;
    if (i < BHh * Mm)       g_ksum[i] = 0.0f;
    if (i < BHh)            g_kmax[i] = -3.0e38f;
}

// -------------------- QKV projection: C[r,e] = sum_d A[r,d]*W[e,d] --------------------
// 128x128 tile, K-step 32, 256 threads, 8x8 micro tiles. Output written into
// (b,h,n,dh) layout.  sel: 0->g_q, 1->g_k, 2->g_v
__global__ __launch_bounds__(256) void k_proj(const float* __restrict__ A,
                                              const float* __restrict__ W, int sel) {
    __shared__ float As[32][132];
    __shared__ float Ws[32][132];
    float* outp = (sel == 0) ? g_q : (sel == 1) ? g_k : g_v;

    int tid = threadIdx.x;
    int r0 = blockIdx.x * 128;
    int e0 = blockIdx.y * 128;
    float acc[8][8];
#pragma unroll
    for (int i = 0; i < 8; i++)
#pragma unroll
        for (int j = 0; j < 8; j++) acc[i][j] = 0.0f;

    for (int k0 = 0; k0 < Dd; k0 += 32) {
#pragma unroll
        for (int i = 0; i < 4; i++) {
            int s = tid + i * 256;
            int row = s >> 3;
            int kc = (s & 7) << 2;
            float4 a = *(const float4*)(A + (size_t)(r0 + row) * Dd + k0 + kc);
            As[kc + 0][row] = a.x; As[kc + 1][row] = a.y;
            As[kc + 2][row] = a.z; As[kc + 3][row] = a.w;
            float4 w = *(const float4*)(W + (size_t)(e0 + row) * Dd + k0 + kc);
            Ws[kc + 0][row] = w.x; Ws[kc + 1][row] = w.y;
            Ws[kc + 2][row] = w.z; Ws[kc + 3][row] = w.w;
        }
        __syncthreads();
        int ty = tid >> 4, tx = tid & 15;
#pragma unroll
        for (int kk = 0; kk < 32; kk++) {
            float4 a0 = *(const float4*)&As[kk][ty * 8];
            float4 a1 = *(const float4*)&As[kk][ty * 8 + 4];
            float4 b0 = *(const float4*)&Ws[kk][tx * 8];
            float4 b1 = *(const float4*)&Ws[kk][tx * 8 + 4];
            float ar[8] = {a0.x, a0.y, a0.z, a0.w, a1.x, a1.y, a1.z, a1.w};
            float br[8] = {b0.x, b0.y, b0.z, b0.w, b1.x, b1.y, b1.z, b1.w};
#pragma unroll
            for (int i = 0; i < 8; i++)
#pragma unroll
                for (int j = 0; j < 8; j++) acc[i][j] = fmaf(ar[i], br[j], acc[i][j]);
        }
        __syncthreads();
    }
    int ty = tid >> 4, tx = tid & 15;
#pragma unroll
    for (int i = 0; i < 8; i++) {
        int r = r0 + ty * 8 + i;
        int b = r >> 12, n = r & 4095;
#pragma unroll
        for (int j = 0; j < 8; j++) {
            int e = e0 + tx * 8 + j;
            int h = e >> 6, dh = e & 63;
            outp[((size_t)(b * Hh + h) * Nn + n) * DHd + dh] = acc[i][j];
        }
    }
}

// -------------------- final: y = x + attn @ Wo^T + bo --------------------
__global__ __launch_bounds__(256) void k_final(const float* __restrict__ W,
                                               const float* __restrict__ x,
                                               const float* __restrict__ bo,
                                               float* __restrict__ out) {
    __shared__ float As[32][132];
    __shared__ float Ws[32][132];
    int tid = threadIdx.x;
    int r0 = blockIdx.x * 128;
    int e0 = blockIdx.y * 128;
    float acc[8][8];
#pragma unroll
    for (int i = 0; i < 8; i++)
#pragma unroll
        for (int j = 0; j < 8; j++) acc[i][j] = 0.0f;

    for (int k0 = 0; k0 < Dd; k0 += 32) {
#pragma unroll
        for (int i = 0; i < 4; i++) {
            int s = tid + i * 256;
            int row = s >> 3;
            int kc = (s & 7) << 2;
            float4 a = *(const float4*)(g_attn + (size_t)(r0 + row) * Dd + k0 + kc);
            As[kc + 0][row] = a.x; As[kc + 1][row] = a.y;
            As[kc + 2][row] = a.z; As[kc + 3][row] = a.w;
            float4 w = *(const float4*)(W + (size_t)(e0 + row) * Dd + k0 + kc);
            Ws[kc + 0][row] = w.x; Ws[kc + 1][row] = w.y;
            Ws[kc + 2][row] = w.z; Ws[kc + 3][row] = w.w;
        }
        __syncthreads();
        int ty = tid >> 4, tx = tid & 15;
#pragma unroll
        for (int kk = 0; kk < 32; kk++) {
            float4 a0 = *(const float4*)&As[kk][ty * 8];
            float4 a1 = *(const float4*)&As[kk][ty * 8 + 4];
            float4 b0 = *(const float4*)&Ws[kk][tx * 8];
            float4 b1 = *(const float4*)&Ws[kk][tx * 8 + 4];
            float ar[8] = {a0.x, a0.y, a0.z, a0.w, a1.x, a1.y, a1.z, a1.w};
            float br[8] = {b0.x, b0.y, b0.z, b0.w, b1.x, b1.y, b1.z, b1.w};
#pragma unroll
            for (int i = 0; i < 8; i++)
#pragma unroll
                for (int j = 0; j < 8; j++) acc[i][j] = fmaf(ar[i], br[j], acc[i][j]);
        }
        __syncthreads();
    }
    int ty = tid >> 4, tx = tid & 15;
#pragma unroll
    for (int i = 0; i < 8; i++) {
        int r = r0 + ty * 8 + i;
#pragma unroll
        for (int j = 0; j < 8; j++) {
            int e = e0 + tx * 8 + j;
            out[(size_t)r * Dd + e] = x[(size_t)r * Dd + e] + bo[e] + acc[i][j];
        }
    }
}

// -------------------- phi_k pass 1: td = (k*nrm)@proj^T, diag, per-head max --------------------
__global__ __launch_bounds__(256) void k_phi_k(const float* __restrict__ proj) {
    __shared__ float Ks[64][68];   // [dh][n]
    __shared__ float Ps[64][68];   // [dh][m]
    __shared__ float red[256];
    int tid = threadIdx.x;
    int n0 = blockIdx.x * 64;
    int m0 = blockIdx.y * 64;
    int bh = blockIdx.z;

#pragma unroll
    for (int i = 0; i < 4; i++) {
        int s = tid + i * 256;
        int row = s >> 4;
        int kc = (s & 15) << 2;
        float4 a = *(const float4*)(g_k + ((size_t)bh * Nn + n0 + row) * DHd + kc);
        Ks[kc + 0][row] = a.x * NORMALIZER; Ks[kc + 1][row] = a.y * NORMALIZER;
        Ks[kc + 2][row] = a.z * NORMALIZER; Ks[kc + 3][row] = a.w * NORMALIZER;
        float4 p = make_float4(0.f, 0.f, 0.f, 0.f);
        if (m0 + row < Mm) p = *(const float4*)(proj + (size_t)(m0 + row) * DHd + kc);
        Ps[kc + 0][row] = p.x; Ps[kc + 1][row] = p.y;
        Ps[kc + 2][row] = p.z; Ps[kc + 3][row] = p.w;
    }
    __syncthreads();

    if (m0 == 0 && tid < 64) {
        float ss = 0.f;
#pragma unroll
        for (int d = 0; d < 64; d++) { float q = Ks[d][tid]; ss += q * q; }
        g_diag[(size_t)bh * Nn + n0 + tid] = 0.5f * ss;
    }

    float acc[4][4];
#pragma unroll
    for (int i = 0; i < 4; i++)
#pragma unroll
        for (int j = 0; j < 4; j++) acc[i][j] = 0.f;
    int ty = tid >> 4, tx = tid & 15;
#pragma unroll
    for (int kk = 0; kk < 64; kk++) {
        float4 a = *(const float4*)&Ks[kk][ty * 4];
        float4 b = *(const float4*)&Ps[kk][tx * 4];
        float ar[4] = {a.x, a.y, a.z, a.w};
        float br[4] = {b.x, b.y, b.z, b.w};
#pragma unroll
        for (int i = 0; i < 4; i++)
#pragma unroll
            for (int j = 0; j < 4; j++) acc[i][j] = fmaf(ar[i], br[j], acc[i][j]);
    }

    float mymax = -3.0e38f;
#pragma unroll
    for (int i = 0; i < 4; i++) {
        int n = n0 + ty * 4 + i;
#pragma unroll
        for (int j = 0; j < 4; j++) {
            int m = m0 + tx * 4 + j;
            if (m < Mm) {
                g_kp[((size_t)bh * Nn + n) * Mm + m] = acc[i][j];
                mymax = fmaxf(mymax, acc[i][j]);
            }
        }
    }
    red[tid] = mymax;
    __syncthreads();
    for (int off = 128; off > 0; off >>= 1) {
        if (tid < off) red[tid] = fmaxf(red[tid], red[tid + off]);
        __syncthreads();
    }
    if (tid == 0) atomicMaxF(&g_kmax[bh], red[0]);
}

// -------------------- phi_k pass 2: exp + column sums --------------------
__global__ __launch_bounds__(256) void k_exp_k() {
    __shared__ float diag_s[64];
    int tid = threadIdx.x;
    int n0 = blockIdx.x * 64;
    int bh = blockIdx.y;
    if (tid < 64) diag_s[tid] = g_diag[(size_t)bh * Nn + n0 + tid];
    __syncthreads();
    float mx = g_kmax[bh];
    for (int m = tid; m < Mm; m += 256) {
        size_t base = ((size_t)bh * Nn + n0) * Mm + m;
        float cs = 0.f;
#pragma unroll 4
        for (int r = 0; r < 64; r++) {
            float td = g_kp[base + (size_t)r * Mm];
            float v = RATIO * (fast_exp(td - diag_s[r] - mx) + EPSF);
            g_kp[base + (size_t)r * Mm] = v;
            cs += v;
        }
        atomicAdd(&g_ksum[bh * Mm + m], cs);
    }
}

// -------------------- phi_q fully fused: td -> rowmax -> exp -> qp + d_inv --------------------
#define QP_SMEM_FLOATS (4352 + 4352 + 17152 + MPAD + 64)
__global__ __launch_bounds__(256) void k_phi_q(const float* __restrict__ proj) {
    extern __shared__ float sm[];
    float* Qs     = sm;                       // 64*68  [dh][n]
    float* Ps     = sm + 4352;                // 64*68  [dh][m]
    float* tds    = sm + 8704;                // 64*MPAD
    float* ksum_s = sm + 8704 + 17152;        // MPAD
    float* diag_s = ksum_s + MPAD;            // 64

    int tid = threadIdx.x;
    int n0 = blockIdx.x * 64;
    int bh = blockIdx.y;

    for (int i = tid; i < Mm; i += 256) ksum_s[i] = g_ksum[bh * Mm + i];

#pragma unroll
    for (int i = 0; i < 4; i++) {
        int s = tid + i * 256;
        int row = s >> 4;
        int kc = (s & 15) << 2;
        float4 a = *(const float4*)(g_q + ((size_t)bh * Nn + n0 + row) * DHd + kc);
        Qs[(kc + 0) * 68 + row] = a.x * NORMALIZER;
        Qs[(kc + 1) * 68 + row] = a.y * NORMALIZER;
        Qs[(kc + 2) * 68 + row] = a.z * NORMALIZER;
        Qs[(kc + 3) * 68 + row] = a.w * NORMALIZER;
    }
    __syncthreads();
    if (tid < 64) {
        float ss = 0.f;
#pragma unroll
        for (int d = 0; d < 64; d++) { float q = Qs[d * 68 + tid]; ss += q * q; }
        diag_s[tid] = 0.5f * ss;
    }

    int ty = tid >> 4, tx = tid & 15;
    for (int mt = 0; mt < 5; mt++) {
        int m0 = mt * 64;
#pragma unroll
        for (int i = 0; i < 4; i++) {
            int s = tid + i * 256;
            int row = s >> 4;
            int kc = (s & 15) << 2;
            float4 p = make_float4(0.f, 0.f, 0.f, 0.f);
            if (m0 + row < Mm) p = *(const float4*)(proj + (size_t)(m0 + row) * DHd + kc);
            Ps[(kc + 0) * 68 + row] = p.x;
            Ps[(kc + 1) * 68 + row] = p.y;
            Ps[(kc + 2) * 68 + row] = p.z;
            Ps[(kc + 3) * 68 + row] = p.w;
        }
        __syncthreads();
        float acc[4][4];
#pragma unroll
        for (int i = 0; i < 4; i++)
#pragma unroll
            for (int j = 0; j < 4; j++) acc[i][j] = 0.f;
#pragma unroll
        for (int kk = 0; kk < 64; kk++) {
            float4 a = *(const float4*)&Qs[kk * 68 + ty * 4];
            float4 b = *(const float4*)&Ps[kk * 68 + tx * 4];
            float ar[4] = {a.x, a.y, a.z, a.w};
            float br[4] = {b.x, b.y, b.z, b.w};
#pragma unroll
            for (int i = 0; i < 4; i++)
#pragma unroll
                for (int j = 0; j < 4; j++) acc[i][j] = fmaf(ar[i], br[j], acc[i][j]);
        }
#pragma unroll
        for (int i = 0; i < 4; i++)
#pragma unroll
            for (int j = 0; j < 4; j++) {
                int m = m0 + tx * 4 + j;
                if (m < Mm) tds[(ty * 4 + i) * MPAD + m] = acc[i][j];
            }
        __syncthreads();
    }

    // per-row: max, exp, qp store, d_inv
    int row = tid >> 2, lane = tid & 3;
    float pm = -3.0e38f;
    for (int m = lane; m < Mm; m += 4) pm = fmaxf(pm, tds[row * MPAD + m]);
    pm = fmaxf(pm, __shfl_xor_sync(0xffffffffu, pm, 1));
    pm = fmaxf(pm, __shfl_xor_sync(0xffffffffu, pm, 2));
    float dg = diag_s[row];
    float sum = 0.f;
    size_t gb = ((size_t)bh * Nn + n0 + row) * Mm;
    for (int m = lane; m < Mm; m += 4) {
        float v = RATIO * (fast_exp(tds[row * MPAD + m] - dg - pm) + EPSF);
        g_qp[gb + m] = v;
        sum += v * ksum_s[m];
    }
    sum += __shfl_xor_sync(0xffffffffu, sum, 1);
    sum += __shfl_xor_sync(0xffffffffu, sum, 2);
    if (lane == 0) g_dinv[(size_t)bh * Nn + n0 + row] = 1.0f / sum;
}

// -------------------- context: ctx[m,dh] += sum_n kp[n,m]*v[n,dh] (split-K over n) --------------------
__global__ __launch_bounds__(256) void k_ctx() {
    __shared__ float Ksm[64][68];  // [n][m]
    __shared__ float Vs[64][68];   // [n][dh]
    int tid = threadIdx.x;
    int m0 = blockIdx.x * 64;
    int nc = blockIdx.y * 512;
    int bh = blockIdx.z;
    float acc[4][4];
#pragma unroll
    for (int i = 0; i < 4; i++)
#pragma unroll
        for (int j = 0; j < 4; j++) acc[i][j] = 0.f;
    int ty = tid >> 4, tx = tid & 15;

    for (int n0 = nc; n0 < nc + 512; n0 += 64) {
#pragma unroll
        for (int i = 0; i < 16; i++) {
            int s = tid + i * 256;
            int n = s >> 6, mm = s & 63;
            Ksm[n][mm] = (m0 + mm < Mm)
                             ? g_kp[((size_t)bh * Nn + n0 + n) * Mm + m0 + mm]
                             : 0.f;
        }
#pragma unroll
        for (int i = 0; i < 4; i++) {
            int s = tid + i * 256;
            int n = s >> 4, c = (s & 15) << 2;
            float4 v = *(const float4*)(g_v + ((size_t)bh * Nn + n0 + n) * DHd + c);
            Vs[n][c] = v.x; Vs[n][c + 1] = v.y; Vs[n][c + 2] = v.z; Vs[n][c + 3] = v.w;
        }
        __syncthreads();
#pragma unroll
        for (int kk = 0; kk < 64; kk++) {
            float4 a = *(const float4*)&Ksm[kk][ty * 4];
            float4 b = *(const float4*)&Vs[kk][tx * 4];
            float ar[4] = {a.x, a.y, a.z, a.w};
            float br[4] = {b.x, b.y, b.z, b.w};
#pragma unroll
            for (int i = 0; i < 4; i++)
#pragma unroll
                for (int j = 0; j < 4; j++) acc[i][j] = fmaf(ar[i], br[j], acc[i][j]);
        }
        __syncthreads();
    }
#pragma unroll
    for (int i = 0; i < 4; i++) {
        int m = m0 + ty * 4 + i;
        if (m < Mm)
#pragma unroll
            for (int j = 0; j < 4; j++)
                atomicAdd(&g_ctx[((size_t)bh * Mm + m) * DHd + tx * 4 + j], acc[i][j]);
    }
}

// -------------------- out: attn[n, h*64+dh] = d_inv[n] * sum_m qp[n,m]*ctx[m,dh] --------------------
__global__ __launch_bounds__(256) void k_out() {
    __shared__ float Qs[64][68];  // [k][n]
    __shared__ float Cs[64][68];  // [k][dh]
    int tid = threadIdx.x;
    int n0 = blockIdx.x * 64;
    int bh = blockIdx.y;
    float acc[4][4];
#pragma unroll
    for (int i = 0; i < 4; i++)
#pragma unroll
        for (int j = 0; j < 4; j++) acc[i][j] = 0.f;
    int ty = tid >> 4, tx = tid & 15;

    for (int c0 = 0; c0 < Mm; c0 += 64) {
#pragma unroll
        for (int i = 0; i < 16; i++) {
            int s = tid + i * 256;
            int r = s >> 6, kc = s & 63;
            Qs[kc][r] = (c0 + kc < Mm)
                            ? g_qp[((size_t)bh * Nn + n0 + r) * Mm + c0 + kc]
                            : 0.f;
        }
#pragma unroll
        for (int i = 0; i < 16; i++) {
            int s = tid + i * 256;
            int kk = s >> 6, dh = s & 63;
            Cs[kk][dh] = (c0 + kk < Mm)
                             ? g_ctx[((size_t)bh * Mm + c0 + kk) * DHd + dh]
                             : 0.f;
        }
        __syncthreads();
#pragma unroll
        for (int kk = 0; kk < 64; kk++) {
            float4 a = *(const float4*)&Qs[kk][ty * 4];
            float4 b = *(const float4*)&Cs[kk][tx * 4];
            float ar[4] = {a.x, a.y, a.z, a.w};
            float br[4] = {b.x, b.y, b.z, b.w};
#pragma unroll
            for (int i = 0; i < 4; i++)
#pragma unroll
                for (int j = 0; j < 4; j++) acc[i][j] = fmaf(ar[i], br[j], acc[i][j]);
        }
        __syncthreads();
    }
    int b = bh >> 3, h = bh & 7;
#pragma unroll
    for (int i = 0; i < 4; i++) {
        int n = n0 + ty * 4 + i;
        float dv = g_dinv[(size_t)bh * Nn + n];
#pragma unroll
        for (int j = 0; j < 4; j++)
            g_attn[((size_t)(b * Nn + n)) * Dd + h * 64 + tx * 4 + j] = acc[i][j] * dv;
    }
}

// -------------------- launch --------------------
extern "C" void kernel_launch(void* const* d_in, const int* in_sizes, int n_in,
                              void* d_out, int out_size) {
    const float* x    = (const float*)d_in[0];
    const float* Wq   = (const float*)d_in[1];
    const float* Wk   = (const float*)d_in[2];
    const float* Wv   = (const float*)d_in[3];
    const float* Wo   = (const float*)d_in[4];
    const float* bo   = (const float*)d_in[5];
    const float* proj = (const float*)d_in[6];
    float* out = (float*)d_out;
    (void)in_sizes; (void)n_in; (void)out_size;

    cudaFuncSetAttribute(k_phi_q, cudaFuncAttributeMaxDynamicSharedMemorySize,
                         QP_SMEM_FLOATS * (int)sizeof(float));

    k_init<<<(BHh * Mm * DHd + 255) / 256, 256>>>();

    dim3 gP(BNn / 128, Dd / 128);
    k_proj<<<gP, 256>>>(x, Wq, 0);
    k_proj<<<gP, 256>>>(x, Wk, 1);
    k_proj<<<gP, 256>>>(x, Wv, 2);

    k_phi_k<<<dim3(Nn / 64, 5, BHh), 256>>>(proj);
    k_exp_k<<<dim3(Nn / 64, BHh), 256>>>();
    k_phi_q<<<dim3(Nn / 64, BHh), 256, QP_SMEM_FLOATS * (int)sizeof(float)>>>(proj);

    k_ctx<<<dim3(5, Nn / 512, BHh), 256>>>();
    k_out<<<dim3(Nn / 64, BHh), 256>>>();

    k_final<<<gP, 256>>>(Wo, x, bo, out);
}

// round 5
// speedup vs baseline: 1.2996x; 1.2996x over previous
#include <cuda_runtime.h>
#include <cuda_bf16.h>
#include <stdint.h>
#include <math.h>

#define Bb   4
#define Nn   4096
#define Dd   512
#define Hh   8
#define DHd  64
#define Mm   266
#define BHh  32          // B*H
#define BNn  16384       // B*N
#define MPAD 268
#define K2   1536        // split-bf16 expanded K (hi|lo|hi)

// -------------------- scratch (static device memory; no allocs) --------------------
__device__ float g_q  [(size_t)BHh * Nn * DHd];
__device__ float g_k  [(size_t)BHh * Nn * DHd];
__device__ float g_v  [(size_t)BHh * Nn * DHd];
__device__ float g_qp [(size_t)BHh * Nn * Mm];
__device__ float g_kp [(size_t)BHh * Nn * Mm];
__device__ float g_ctx [(size_t)BHh * Mm * DHd];
__device__ float g_ksum[(size_t)BHh * Mm];
__device__ float g_kmax[BHh];
__device__ float g_diag[(size_t)BHh * Nn];
__device__ float g_dinv[(size_t)BHh * Nn];

__device__ __nv_bfloat16 g_x2   [(size_t)BNn * K2];
__device__ __nv_bfloat16 g_attn2[(size_t)BNn * K2];
__device__ __nv_bfloat16 g_wq2  [(size_t)Dd * K2];
__device__ __nv_bfloat16 g_wk2  [(size_t)Dd * K2];
__device__ __nv_bfloat16 g_wv2  [(size_t)Dd * K2];
__device__ __nv_bfloat16 g_wo2  [(size_t)Dd * K2];

// -------------------- helpers --------------------
__device__ __forceinline__ uint32_t smem_to_u32(const void* p) {
    uint32_t a;
    asm("{ .reg .u64 t; cvta.to.shared.u64 t, %1; cvt.u32.u64 %0, t; }"
        : "=r"(a) : "l"(p));
    return a;
}

#define CP_ASYNC16(dst, src) \
    asm volatile("cp.async.cg.shared.global [%0], [%1], 16;" \
                 :: "r"(dst), "l"(src) : "memory")
#define CP_COMMIT()  asm volatile("cp.async.commit_group;" ::: "memory")
#define CP_WAIT1()   asm volatile("cp.async.wait_group 1;" ::: "memory")
#define CP_WAIT0()   asm volatile("cp.async.wait_group 0;" ::: "memory")

__device__ __forceinline__ void ldm_x4(uint32_t& r0, uint32_t& r1,
                                       uint32_t& r2, uint32_t& r3, uint32_t addr) {
    asm volatile("ldmatrix.sync.aligned.m8n8.x4.shared.b16 {%0,%1,%2,%3}, [%4];"
                 : "=r"(r0), "=r"(r1), "=r"(r2), "=r"(r3) : "r"(addr));
}

__device__ __forceinline__ void mma16816(float* c, const uint32_t* a, const uint32_t* b) {
    asm volatile(
        "mma.sync.aligned.m16n8k16.row.col.f32.bf16.bf16.f32 "
        "{%0,%1,%2,%3}, {%4,%5,%6,%7}, {%8,%9}, {%0,%1,%2,%3};"
        : "+f"(c[0]), "+f"(c[1]), "+f"(c[2]), "+f"(c[3])
        : "r"(a[0]), "r"(a[1]), "r"(a[2]), "r"(a[3]), "r"(b[0]), "r"(b[1]));
}

__device__ __forceinline__ void atomicMaxF(float* addr, float val) {
    int* ai = (int*)addr;
    int old = *ai;
    while (__int_as_float(old) < val) {
        int assumed = old;
        old = atomicCAS(ai, assumed, __float_as_int(val));
        if (old == assumed) break;
    }
}

__device__ __forceinline__ float fast_exp(float x) {
    float y = fmaxf(x * 1.4426950408889634f, -126.0f);
    float r = rintf(y);
    float f = y - r;
    float p = 1.5403530e-4f;
    p = fmaf(p, f, 1.3333558e-3f);
    p = fmaf(p, f, 9.6181291e-3f);
    p = fmaf(p, f, 5.5504109e-2f);
    p = fmaf(p, f, 2.4022651e-1f);
    p = fmaf(p, f, 6.9314718e-1f);
    p = fmaf(p, f, 1.0f);
    int e = (int)r;
    float s = __int_as_float((e + 127) << 23);
    return p * s;
}

#define NORMALIZER 0.35355339059327373f   // 64^-0.25
#define RATIO      0.061313934f           // 266^-0.5
#define EPSF       1e-4f

// -------------------- init scratch accumulators --------------------
__global__ void k_init() {
    int i = blockIdx.x * 256 + threadIdx.x;
    if (i < BHh * Mm * DHd) g_ctx[i]  = 0.0f;
    if (i < BHh * Mm)       g_ksum[i] = 0.0f;
    if (i < BHh)            g_kmax[i] = -3.0e38f;
}

// -------------------- fp32 -> split bf16 (hi|lo|hi at given offsets) --------------------
__global__ __launch_bounds__(256) void k_split(const float* __restrict__ src,
                                               __nv_bfloat16* __restrict__ dst,
                                               int nrows, int loOff, int dupOff) {
    int i = blockIdx.x * 256 + threadIdx.x;
    int total = nrows * 128;   // 4 floats per thread
    if (i >= total) return;
    int r = i >> 7;
    int c = (i & 127) << 2;
    float4 v = *(const float4*)(src + (size_t)r * 512 + c);
    __nv_bfloat16 h0 = __float2bfloat16(v.x), h1 = __float2bfloat16(v.y);
    __nv_bfloat16 h2 = __float2bfloat16(v.z), h3 = __float2bfloat16(v.w);
    __nv_bfloat16 l0 = __float2bfloat16(v.x - __bfloat162float(h0));
    __nv_bfloat16 l1 = __float2bfloat16(v.y - __bfloat162float(h1));
    __nv_bfloat16 l2 = __float2bfloat16(v.z - __bfloat162float(h2));
    __nv_bfloat16 l3 = __float2bfloat16(v.w - __bfloat162float(h3));
    size_t rb = (size_t)r * K2;
    __nv_bfloat162 H01; H01.x = h0; H01.y = h1;
    __nv_bfloat162 H23; H23.x = h2; H23.y = h3;
    __nv_bfloat162 L01; L01.x = l0; L01.y = l1;
    __nv_bfloat162 L23; L23.x = l2; L23.y = l3;
    *(__nv_bfloat162*)(dst + rb + c)              = H01;
    *(__nv_bfloat162*)(dst + rb + c + 2)          = H23;
    *(__nv_bfloat162*)(dst + rb + loOff + c)      = L01;
    *(__nv_bfloat162*)(dst + rb + loOff + c + 2)  = L23;
    *(__nv_bfloat162*)(dst + rb + dupOff + c)     = H01;
    *(__nv_bfloat162*)(dst + rb + dupOff + c + 2) = H23;
}

// -------------------- mma.sync GEMM: C[16384,512] = A2[16384,K2] @ B2[512,K2]^T --------
// 128x128 tile, BK=32, 256 threads (8 warps, 4x2), m16n8k16 bf16, cp.async double buffer.
// finalmode=0: scatter into (b,h,n,dh) fp32 layout. finalmode=1: C = acc + x + bo.
#define ASTR 40              // padded bf16 per smem row (80B, conflict-free ldmatrix)
#define TILE_B (128 * ASTR)  // bf16 elems per buffer

__global__ __launch_bounds__(256) void k_gemm(const __nv_bfloat16* __restrict__ A,
                                              const __nv_bfloat16* __restrict__ Bw,
                                              float* __restrict__ C,
                                              const float* __restrict__ xres,
                                              const float* __restrict__ bo,
                                              int finalmode) {
    __shared__ __nv_bfloat16 sA[2][TILE_B];
    __shared__ __nv_bfloat16 sB[2][TILE_B];
    int tid = threadIdx.x, lane = tid & 31, w = tid >> 5;
    int m0 = (w & 3) * 32, n0 = (w >> 2) * 64;
    int r0 = blockIdx.x * 128, e0 = blockIdx.y * 128;
    uint32_t sAu = smem_to_u32(sA), sBu = smem_to_u32(sB);

    float acc[2][8][4];
#pragma unroll
    for (int i = 0; i < 2; i++)
#pragma unroll
        for (int j = 0; j < 8; j++)
#pragma unroll
            for (int l = 0; l < 4; l++) acc[i][j][l] = 0.f;

    // loader: each thread owns row tid>>1, 2x16B at col (tid&1)*16 {+0,+8}
    int lrow = tid >> 1;
    int lcol = (tid & 1) << 4;
    const __nv_bfloat16* Arow = A + (size_t)(r0 + lrow) * K2 + lcol;
    const __nv_bfloat16* Brow = Bw + (size_t)(e0 + lrow) * K2 + lcol;
    uint32_t sAdst = sAu + (uint32_t)(lrow * ASTR + lcol) * 2;
    uint32_t sBdst = sBu + (uint32_t)(lrow * ASTR + lcol) * 2;

#define LOAD_TILE(buf, t) do {                                         \
    uint32_t _o = (uint32_t)(buf) * (TILE_B * 2);                      \
    const __nv_bfloat16* _a = Arow + (t) * 32;                         \
    const __nv_bfloat16* _b = Brow + (t) * 32;                         \
    CP_ASYNC16(sAdst + _o,      _a);                                   \
    CP_ASYNC16(sAdst + _o + 16, _a + 8);                               \
    CP_ASYNC16(sBdst + _o,      _b);                                   \
    CP_ASYNC16(sBdst + _o + 16, _b + 8);                               \
} while (0)

    LOAD_TILE(0, 0);
    CP_COMMIT();

    const int NT = K2 / 32;   // 48
#pragma unroll 1
    for (int t = 0; t < NT; ++t) {
        int buf = t & 1;
        if (t + 1 < NT) {
            LOAD_TILE(buf ^ 1, t + 1);
            CP_COMMIT();
            CP_WAIT1();
        } else {
            CP_WAIT0();
        }
        __syncthreads();

        uint32_t ab = sAu + (uint32_t)buf * (TILE_B * 2);
        uint32_t bb = sBu + (uint32_t)buf * (TILE_B * 2);
#pragma unroll
        for (int ks = 0; ks < 32; ks += 16) {
            uint32_t a[2][4];
#pragma unroll
            for (int mt = 0; mt < 2; mt++) {
                uint32_t addr = ab +
                    (uint32_t)((m0 + mt * 16 + (lane & 15)) * ASTR + ks + ((lane >> 4) << 3)) * 2;
                ldm_x4(a[mt][0], a[mt][1], a[mt][2], a[mt][3], addr);
            }
            uint32_t b[8][2];
#pragma unroll
            for (int p = 0; p < 4; p++) {
                int nA = n0 + p * 16;
                uint32_t addr = bb +
                    (uint32_t)((nA + (lane & 7) + ((lane >> 4) << 3)) * ASTR + ks + (lane & 8)) * 2;
                ldm_x4(b[2 * p][0], b[2 * p][1], b[2 * p + 1][0], b[2 * p + 1][1], addr);
            }
#pragma unroll
            for (int mt = 0; mt < 2; mt++)
#pragma unroll
                for (int nt = 0; nt < 8; nt++)
                    mma16816(acc[mt][nt], a[mt], b[nt]);
        }
        __syncthreads();
    }

    // epilogue
    int gid = lane >> 2, tig = lane & 3;
#pragma unroll
    for (int mt = 0; mt < 2; mt++) {
#pragma unroll
        for (int nt = 0; nt < 8; nt++) {
            int r = r0 + m0 + mt * 16 + gid;
            int e = e0 + n0 + nt * 8 + tig * 2;
            float2 v01 = make_float2(acc[mt][nt][0], acc[mt][nt][1]);
            float2 v23 = make_float2(acc[mt][nt][2], acc[mt][nt][3]);
            if (!finalmode) {
                int b = r >> 12, n = r & 4095;
                int h = e >> 6, dh = e & 63;
                float* d0 = C + (((size_t)((b << 3) + h) * Nn + n) * DHd + dh);
                *(float2*)d0 = v01;
                *(float2*)(d0 + 8 * DHd) = v23;   // row r+8, same b/h
            } else {
                size_t b0 = (size_t)r * Dd + e;
                float2 x0 = *(const float2*)(xres + b0);
                float2 x1 = *(const float2*)(xres + b0 + 8 * Dd);
                float2 bv = *(const float2*)(bo + e);
                float2 o0 = make_float2(x0.x + bv.x + v01.x, x0.y + bv.y + v01.y);
                float2 o1 = make_float2(x1.x + bv.x + v23.x, x1.y + bv.y + v23.y);
                *(float2*)(C + b0) = o0;
                *(float2*)(C + b0 + 8 * Dd) = o1;
            }
        }
    }
}

// -------------------- phi_k pass 1: td = (k*nrm)@proj^T, diag, per-head max --------------------
__global__ __launch_bounds__(256) void k_phi_k(const float* __restrict__ proj) {
    __shared__ float Ks[64][68];   // [dh][n]
    __shared__ float Ps[64][68];   // [dh][m]
    __shared__ float red[256];
    int tid = threadIdx.x;
    int n0 = blockIdx.x * 64;
    int m0 = blockIdx.y * 64;
    int bh = blockIdx.z;

#pragma unroll
    for (int i = 0; i < 4; i++) {
        int s = tid + i * 256;
        int row = s >> 4;
        int kc = (s & 15) << 2;
        float4 a = *(const float4*)(g_k + ((size_t)bh * Nn + n0 + row) * DHd + kc);
        Ks[kc + 0][row] = a.x * NORMALIZER; Ks[kc + 1][row] = a.y * NORMALIZER;
        Ks[kc + 2][row] = a.z * NORMALIZER; Ks[kc + 3][row] = a.w * NORMALIZER;
        float4 p = make_float4(0.f, 0.f, 0.f, 0.f);
        if (m0 + row < Mm) p = *(const float4*)(proj + (size_t)(m0 + row) * DHd + kc);
        Ps[kc + 0][row] = p.x; Ps[kc + 1][row] = p.y;
        Ps[kc + 2][row] = p.z; Ps[kc + 3][row] = p.w;
    }
    __syncthreads();

    if (m0 == 0 && tid < 64) {
        float ss = 0.f;
#pragma unroll
        for (int d = 0; d < 64; d++) { float q = Ks[d][tid]; ss += q * q; }
        g_diag[(size_t)bh * Nn + n0 + tid] = 0.5f * ss;
    }

    float acc[4][4];
#pragma unroll
    for (int i = 0; i < 4; i++)
#pragma unroll
        for (int j = 0; j < 4; j++) acc[i][j] = 0.f;
    int ty = tid >> 4, tx = tid & 15;
#pragma unroll
    for (int kk = 0; kk < 64; kk++) {
        float4 a = *(const float4*)&Ks[kk][ty * 4];
        float4 b = *(const float4*)&Ps[kk][tx * 4];
        float ar[4] = {a.x, a.y, a.z, a.w};
        float br[4] = {b.x, b.y, b.z, b.w};
#pragma unroll
        for (int i = 0; i < 4; i++)
#pragma unroll
            for (int j = 0; j < 4; j++) acc[i][j] = fmaf(ar[i], br[j], acc[i][j]);
    }

    float mymax = -3.0e38f;
#pragma unroll
    for (int i = 0; i < 4; i++) {
        int n = n0 + ty * 4 + i;
#pragma unroll
        for (int j = 0; j < 4; j++) {
            int m = m0 + tx * 4 + j;
            if (m < Mm) {
                g_kp[((size_t)bh * Nn + n) * Mm + m] = acc[i][j];
                mymax = fmaxf(mymax, acc[i][j]);
            }
        }
    }
    red[tid] = mymax;
    __syncthreads();
    for (int off = 128; off > 0; off >>= 1) {
        if (tid < off) red[tid] = fmaxf(red[tid], red[tid + off]);
        __syncthreads();
    }
    if (tid == 0) atomicMaxF(&g_kmax[bh], red[0]);
}

// -------------------- phi_k pass 2: exp + column sums --------------------
__global__ __launch_bounds__(256) void k_exp_k() {
    __shared__ float diag_s[64];
    int tid = threadIdx.x;
    int n0 = blockIdx.x * 64;
    int bh = blockIdx.y;
    if (tid < 64) diag_s[tid] = g_diag[(size_t)bh * Nn + n0 + tid];
    __syncthreads();
    float mx = g_kmax[bh];
    for (int m = tid; m < Mm; m += 256) {
        size_t base = ((size_t)bh * Nn + n0) * Mm + m;
        float cs = 0.f;
#pragma unroll 4
        for (int r = 0; r < 64; r++) {
            float td = g_kp[base + (size_t)r * Mm];
            float v = RATIO * (fast_exp(td - diag_s[r] - mx) + EPSF);
            g_kp[base + (size_t)r * Mm] = v;
            cs += v;
        }
        atomicAdd(&g_ksum[bh * Mm + m], cs);
    }
}

// -------------------- phi_q fully fused: td -> rowmax -> exp -> qp + d_inv --------------------
#define QP_SMEM_FLOATS (4352 + 4352 + 17152 + MPAD + 64)
__global__ __launch_bounds__(256) void k_phi_q(const float* __restrict__ proj) {
    extern __shared__ float sm[];
    float* Qs     = sm;                       // 64*68  [dh][n]
    float* Ps     = sm + 4352;                // 64*68  [dh][m]
    float* tds    = sm + 8704;                // 64*MPAD
    float* ksum_s = sm + 8704 + 17152;        // MPAD
    float* diag_s = ksum_s + MPAD;            // 64

    int tid = threadIdx.x;
    int n0 = blockIdx.x * 64;
    int bh = blockIdx.y;

    for (int i = tid; i < Mm; i += 256) ksum_s[i] = g_ksum[bh * Mm + i];

#pragma unroll
    for (int i = 0; i < 4; i++) {
        int s = tid + i * 256;
        int row = s >> 4;
        int kc = (s & 15) << 2;
        float4 a = *(const float4*)(g_q + ((size_t)bh * Nn + n0 + row) * DHd + kc);
        Qs[(kc + 0) * 68 + row] = a.x * NORMALIZER;
        Qs[(kc + 1) * 68 + row] = a.y * NORMALIZER;
        Qs[(kc + 2) * 68 + row] = a.z * NORMALIZER;
        Qs[(kc + 3) * 68 + row] = a.w * NORMALIZER;
    }
    __syncthreads();
    if (tid < 64) {
        float ss = 0.f;
#pragma unroll
        for (int d = 0; d < 64; d++) { float q = Qs[d * 68 + tid]; ss += q * q; }
        diag_s[tid] = 0.5f * ss;
    }

    int ty = tid >> 4, tx = tid & 15;
    for (int mt = 0; mt < 5; mt++) {
        int m0 = mt * 64;
#pragma unroll
        for (int i = 0; i < 4; i++) {
            int s = tid + i * 256;
            int row = s >> 4;
            int kc = (s & 15) << 2;
            float4 p = make_float4(0.f, 0.f, 0.f, 0.f);
            if (m0 + row < Mm) p = *(const float4*)(proj + (size_t)(m0 + row) * DHd + kc);
            Ps[(kc + 0) * 68 + row] = p.x;
            Ps[(kc + 1) * 68 + row] = p.y;
            Ps[(kc + 2) * 68 + row] = p.z;
            Ps[(kc + 3) * 68 + row] = p.w;
        }
        __syncthreads();
        float acc[4][4];
#pragma unroll
        for (int i = 0; i < 4; i++)
#pragma unroll
            for (int j = 0; j < 4; j++) acc[i][j] = 0.f;
#pragma unroll
        for (int kk = 0; kk < 64; kk++) {
            float4 a = *(const float4*)&Qs[kk * 68 + ty * 4];
            float4 b = *(const float4*)&Ps[kk * 68 + tx * 4];
            float ar[4] = {a.x, a.y, a.z, a.w};
            float br[4] = {b.x, b.y, b.z, b.w};
#pragma unroll
            for (int i = 0; i < 4; i++)
#pragma unroll
                for (int j = 0; j < 4; j++) acc[i][j] = fmaf(ar[i], br[j], acc[i][j]);
        }
#pragma unroll
        for (int i = 0; i < 4; i++)
#pragma unroll
            for (int j = 0; j < 4; j++) {
                int m = m0 + tx * 4 + j;
                if (m < Mm) tds[(ty * 4 + i) * MPAD + m] = acc[i][j];
            }
        __syncthreads();
    }

    int row = tid >> 2, lane = tid & 3;
    float pm = -3.0e38f;
    for (int m = lane; m < Mm; m += 4) pm = fmaxf(pm, tds[row * MPAD + m]);
    pm = fmaxf(pm, __shfl_xor_sync(0xffffffffu, pm, 1));
    pm = fmaxf(pm, __shfl_xor_sync(0xffffffffu, pm, 2));
    float dg = diag_s[row];
    float sum = 0.f;
    size_t gb = ((size_t)bh * Nn + n0 + row) * Mm;
    for (int m = lane; m < Mm; m += 4) {
        float v = RATIO * (fast_exp(tds[row * MPAD + m] - dg - pm) + EPSF);
        g_qp[gb + m] = v;
        sum += v * ksum_s[m];
    }
    sum += __shfl_xor_sync(0xffffffffu, sum, 1);
    sum += __shfl_xor_sync(0xffffffffu, sum, 2);
    if (lane == 0) g_dinv[(size_t)bh * Nn + n0 + row] = 1.0f / sum;
}

// -------------------- context: ctx[m,dh] += sum_n kp[n,m]*v[n,dh] (split-K over n) --------------------
__global__ __launch_bounds__(256) void k_ctx() {
    __shared__ float Ksm[64][68];  // [n][m]
    __shared__ float Vs[64][68];   // [n][dh]
    int tid = threadIdx.x;
    int m0 = blockIdx.x * 64;
    int nc = blockIdx.y * 512;
    int bh = blockIdx.z;
    float acc[4][4];
#pragma unroll
    for (int i = 0; i < 4; i++)
#pragma unroll
        for (int j = 0; j < 4; j++) acc[i][j] = 0.f;
    int ty = tid >> 4, tx = tid & 15;

    for (int n0 = nc; n0 < nc + 512; n0 += 64) {
#pragma unroll
        for (int i = 0; i < 16; i++) {
            int s = tid + i * 256;
            int n = s >> 6, mm = s & 63;
            Ksm[n][mm] = (m0 + mm < Mm)
                             ? g_kp[((size_t)bh * Nn + n0 + n) * Mm + m0 + mm]
                             : 0.f;
        }
#pragma unroll
        for (int i = 0; i < 4; i++) {
            int s = tid + i * 256;
            int n = s >> 4, c = (s & 15) << 2;
            float4 v = *(const float4*)(g_v + ((size_t)bh * Nn + n0 + n) * DHd + c);
            Vs[n][c] = v.x; Vs[n][c + 1] = v.y; Vs[n][c + 2] = v.z; Vs[n][c + 3] = v.w;
        }
        __syncthreads();
#pragma unroll
        for (int kk = 0; kk < 64; kk++) {
            float4 a = *(const float4*)&Ksm[kk][ty * 4];
            float4 b = *(const float4*)&Vs[kk][tx * 4];
            float ar[4] = {a.x, a.y, a.z, a.w};
            float br[4] = {b.x, b.y, b.z, b.w};
#pragma unroll
            for (int i = 0; i < 4; i++)
#pragma unroll
                for (int j = 0; j < 4; j++) acc[i][j] = fmaf(ar[i], br[j], acc[i][j]);
        }
        __syncthreads();
    }
#pragma unroll
    for (int i = 0; i < 4; i++) {
        int m = m0 + ty * 4 + i;
        if (m < Mm)
#pragma unroll
            for (int j = 0; j < 4; j++)
                atomicAdd(&g_ctx[((size_t)bh * Mm + m) * DHd + tx * 4 + j], acc[i][j]);
    }
}

// -------------------- out: attn2 (split bf16) = d_inv[n] * sum_m qp[n,m]*ctx[m,dh] --------------------
__global__ __launch_bounds__(256) void k_out() {
    __shared__ float Qs[64][68];  // [k][n]
    __shared__ float Cs[64][68];  // [k][dh]
    int tid = threadIdx.x;
    int n0 = blockIdx.x * 64;
    int bh = blockIdx.y;
    float acc[4][4];
#pragma unroll
    for (int i = 0; i < 4; i++)
#pragma unroll
        for (int j = 0; j < 4; j++) acc[i][j] = 0.f;
    int ty = tid >> 4, tx = tid & 15;

    for (int c0 = 0; c0 < Mm; c0 += 64) {
#pragma unroll
        for (int i = 0; i < 16; i++) {
            int s = tid + i * 256;
            int r = s >> 6, kc = s & 63;
            Qs[kc][r] = (c0 + kc < Mm)
                            ? g_qp[((size_t)bh * Nn + n0 + r) * Mm + c0 + kc]
                            : 0.f;
        }
#pragma unroll
        for (int i = 0; i < 16; i++) {
            int s = tid + i * 256;
            int kk = s >> 6, dh = s & 63;
            Cs[kk][dh] = (c0 + kk < Mm)
                             ? g_ctx[((size_t)bh * Mm + c0 + kk) * DHd + dh]
                             : 0.f;
        }
        __syncthreads();
#pragma unroll
        for (int kk = 0; kk < 64; kk++) {
            float4 a = *(const float4*)&Qs[kk][ty * 4];
            float4 b = *(const float4*)&Cs[kk][tx * 4];
            float ar[4] = {a.x, a.y, a.z, a.w};
            float br[4] = {b.x, b.y, b.z, b.w};
#pragma unroll
            for (int i = 0; i < 4; i++)
#pragma unroll
                for (int j = 0; j < 4; j++) acc[i][j] = fmaf(ar[i], br[j], acc[i][j]);
        }
        __syncthreads();
    }
    int b = bh >> 3, h = bh & 7;
#pragma unroll
    for (int i = 0; i < 4; i++) {
        int n = n0 + ty * 4 + i;
        float dv = g_dinv[(size_t)bh * Nn + n];
        size_t rb = (size_t)(b * Nn + n) * K2 + h * 64 + tx * 4;
#pragma unroll
        for (int j = 0; j < 4; j++) {
            float val = acc[i][j] * dv;
            __nv_bfloat16 hv = __float2bfloat16(val);
            __nv_bfloat16 lv = __float2bfloat16(val - __bfloat162float(hv));
            g_attn2[rb + j]        = hv;   // hi
            g_attn2[rb + 512 + j]  = lv;   // lo  (pairs with Wo hi)
            g_attn2[rb + 1024 + j] = hv;   // hi  (pairs with Wo lo)
        }
    }
}

// -------------------- launch --------------------
extern "C" void kernel_launch(void* const* d_in, const int* in_sizes, int n_in,
                              void* d_out, int out_size) {
    const float* x    = (const float*)d_in[0];
    const float* Wq   = (const float*)d_in[1];
    const float* Wk   = (const float*)d_in[2];
    const float* Wv   = (const float*)d_in[3];
    const float* Wo   = (const float*)d_in[4];
    const float* bo   = (const float*)d_in[5];
    const float* proj = (const float*)d_in[6];
    float* out = (float*)d_out;
    (void)in_sizes; (void)n_in; (void)out_size;

    cudaFuncSetAttribute(k_phi_q, cudaFuncAttributeMaxDynamicSharedMemorySize,
                         QP_SMEM_FLOATS * (int)sizeof(float));

    __nv_bfloat16 *x2p, *wq2p, *wk2p, *wv2p, *wo2p, *attn2p;
    cudaGetSymbolAddress((void**)&x2p, g_x2);
    cudaGetSymbolAddress((void**)&wq2p, g_wq2);
    cudaGetSymbolAddress((void**)&wk2p, g_wk2);
    cudaGetSymbolAddress((void**)&wv2p, g_wv2);
    cudaGetSymbolAddress((void**)&wo2p, g_wo2);
    cudaGetSymbolAddress((void**)&attn2p, g_attn2);
    float *qp_, *kp_, *vp_;
    cudaGetSymbolAddress((void**)&qp_, g_q);
    cudaGetSymbolAddress((void**)&kp_, g_k);
    cudaGetSymbolAddress((void**)&vp_, g_v);

    k_init<<<(BHh * Mm * DHd + 255) / 256, 256>>>();

    // split fp32 -> (hi|lo|hi) / (hi|hi|lo) bf16
    k_split<<<(BNn * 128 + 255) / 256, 256>>>(x, x2p, BNn, 512, 1024);   // A-layout
    k_split<<<(Dd * 128 + 255) / 256, 256>>>(Wq, wq2p, Dd, 1024, 512);   // W-layout
    k_split<<<(Dd * 128 + 255) / 256, 256>>>(Wk, wk2p, Dd, 1024, 512);
    k_split<<<(Dd * 128 + 255) / 256, 256>>>(Wv, wv2p, Dd, 1024, 512);
    k_split<<<(Dd * 128 + 255) / 256, 256>>>(Wo, wo2p, Dd, 1024, 512);

    dim3 gG(BNn / 128, Dd / 128);
    k_gemm<<<gG, 256>>>(x2p, wq2p, qp_, nullptr, nullptr, 0);
    k_gemm<<<gG, 256>>>(x2p, wk2p, kp_, nullptr, nullptr, 0);
    k_gemm<<<gG, 256>>>(x2p, wv2p, vp_, nullptr, nullptr, 0);

    k_phi_k<<<dim3(Nn / 64, 5, BHh), 256>>>(proj);
    k_exp_k<<<dim3(Nn / 64, BHh), 256>>>();
    k_phi_q<<<dim3(Nn / 64, BHh), 256, QP_SMEM_FLOATS * (int)sizeof(float)>>>(proj);

    k_ctx<<<dim3(5, Nn / 512, BHh), 256>>>();
    k_out<<<dim3(Nn / 64, BHh), 256>>>();

    k_gemm<<<gG, 256>>>(attn2p, wo2p, out, x, bo, 1);
}

// round 6
// speedup vs baseline: 1.3385x; 1.0299x over previous
#include <cuda_runtime.h>
#include <cuda_bf16.h>
#include <stdint.h>
#include <math.h>

#define Bb   4
#define Nn   4096
#define Dd   512
#define Hh   8
#define DHd  64
#define Mm   266
#define BHh  32          // B*H
#define BNn  16384       // B*N
#define MPAD 268
#define K2   1536        // split-bf16 expanded K (hi|lo|hi)

// -------------------- scratch (static device memory; no allocs) --------------------
__device__ float g_q  [(size_t)BHh * Nn * DHd];
__device__ float g_k  [(size_t)BHh * Nn * DHd];
__device__ float g_v  [(size_t)BHh * Nn * DHd];
__device__ float g_qp [(size_t)BHh * Nn * Mm];
__device__ float g_kp [(size_t)BHh * Nn * Mm];
__device__ float g_ctx [(size_t)BHh * Mm * DHd];
__device__ float g_ksum[(size_t)BHh * Mm];
__device__ float g_kmax[BHh];
__device__ float g_diag[(size_t)BHh * Nn];
__device__ float g_dinv[(size_t)BHh * Nn];

__device__ __nv_bfloat16 g_x2   [(size_t)BNn * K2];
__device__ __nv_bfloat16 g_attn2[(size_t)BNn * K2];
__device__ __nv_bfloat16 g_wq2  [(size_t)Dd * K2];
__device__ __nv_bfloat16 g_wk2  [(size_t)Dd * K2];
__device__ __nv_bfloat16 g_wv2  [(size_t)Dd * K2];
__device__ __nv_bfloat16 g_wo2  [(size_t)Dd * K2];

// -------------------- helpers --------------------
__device__ __forceinline__ uint32_t smem_to_u32(const void* p) {
    uint32_t a;
    asm("{ .reg .u64 t; cvta.to.shared.u64 t, %1; cvt.u32.u64 %0, t; }"
        : "=r"(a) : "l"(p));
    return a;
}

#define CP_ASYNC16(dst, src) \
    asm volatile("cp.async.cg.shared.global [%0], [%1], 16;" \
                 :: "r"(dst), "l"(src) : "memory")
#define CP_COMMIT()  asm volatile("cp.async.commit_group;" ::: "memory")
#define CP_WAIT1()   asm volatile("cp.async.wait_group 1;" ::: "memory")
#define CP_WAIT0()   asm volatile("cp.async.wait_group 0;" ::: "memory")

__device__ __forceinline__ void ldm_x4(uint32_t& r0, uint32_t& r1,
                                       uint32_t& r2, uint32_t& r3, uint32_t addr) {
    asm volatile("ldmatrix.sync.aligned.m8n8.x4.shared.b16 {%0,%1,%2,%3}, [%4];"
                 : "=r"(r0), "=r"(r1), "=r"(r2), "=r"(r3) : "r"(addr));
}

__device__ __forceinline__ void mma16816(float* c, const uint32_t* a, const uint32_t* b) {
    asm volatile(
        "mma.sync.aligned.m16n8k16.row.col.f32.bf16.bf16.f32 "
        "{%0,%1,%2,%3}, {%4,%5,%6,%7}, {%8,%9}, {%0,%1,%2,%3};"
        : "+f"(c[0]), "+f"(c[1]), "+f"(c[2]), "+f"(c[3])
        : "r"(a[0]), "r"(a[1]), "r"(a[2]), "r"(a[3]), "r"(b[0]), "r"(b[1]));
}

__device__ __forceinline__ void atomicMaxF(float* addr, float val) {
    int* ai = (int*)addr;
    int old = *ai;
    while (__int_as_float(old) < val) {
        int assumed = old;
        old = atomicCAS(ai, assumed, __float_as_int(val));
        if (old == assumed) break;
    }
}

__device__ __forceinline__ float fast_exp(float x) {
    float y = fmaxf(x * 1.4426950408889634f, -126.0f);
    float r = rintf(y);
    float f = y - r;
    float p = 1.5403530e-4f;
    p = fmaf(p, f, 1.3333558e-3f);
    p = fmaf(p, f, 9.6181291e-3f);
    p = fmaf(p, f, 5.5504109e-2f);
    p = fmaf(p, f, 2.4022651e-1f);
    p = fmaf(p, f, 6.9314718e-1f);
    p = fmaf(p, f, 1.0f);
    int e = (int)r;
    float s = __int_as_float((e + 127) << 23);
    return p * s;
}

#define NORMALIZER 0.35355339059327373f   // 64^-0.25
#define RATIO      0.061313934f           // 266^-0.5
#define EPSF       1e-4f

// -------------------- init scratch accumulators --------------------
__global__ void k_init() {
    int i = blockIdx.x * 256 + threadIdx.x;
    if (i < BHh * Mm * DHd) g_ctx[i]  = 0.0f;
    if (i < BHh * Mm)       g_ksum[i] = 0.0f;
    if (i < BHh)            g_kmax[i] = -3.0e38f;
}

// -------------------- fp32 -> split bf16 (hi|lo|hi at given offsets) --------------------
__global__ __launch_bounds__(256) void k_split(const float* __restrict__ src,
                                               __nv_bfloat16* __restrict__ dst,
                                               int nrows, int loOff, int dupOff) {
    int i = blockIdx.x * 256 + threadIdx.x;
    int total = nrows * 128;   // 4 floats per thread
    if (i >= total) return;
    int r = i >> 7;
    int c = (i & 127) << 2;
    float4 v = *(const float4*)(src + (size_t)r * 512 + c);
    __nv_bfloat16 h0 = __float2bfloat16(v.x), h1 = __float2bfloat16(v.y);
    __nv_bfloat16 h2 = __float2bfloat16(v.z), h3 = __float2bfloat16(v.w);
    __nv_bfloat16 l0 = __float2bfloat16(v.x - __bfloat162float(h0));
    __nv_bfloat16 l1 = __float2bfloat16(v.y - __bfloat162float(h1));
    __nv_bfloat16 l2 = __float2bfloat16(v.z - __bfloat162float(h2));
    __nv_bfloat16 l3 = __float2bfloat16(v.w - __bfloat162float(h3));
    size_t rb = (size_t)r * K2;
    __nv_bfloat162 H01; H01.x = h0; H01.y = h1;
    __nv_bfloat162 H23; H23.x = h2; H23.y = h3;
    __nv_bfloat162 L01; L01.x = l0; L01.y = l1;
    __nv_bfloat162 L23; L23.x = l2; L23.y = l3;
    *(__nv_bfloat162*)(dst + rb + c)              = H01;
    *(__nv_bfloat162*)(dst + rb + c + 2)          = H23;
    *(__nv_bfloat162*)(dst + rb + loOff + c)      = L01;
    *(__nv_bfloat162*)(dst + rb + loOff + c + 2)  = L23;
    *(__nv_bfloat162*)(dst + rb + dupOff + c)     = H01;
    *(__nv_bfloat162*)(dst + rb + dupOff + c + 2) = H23;
}

// -------------------- mma.sync GEMM: C[16384,512] = A2[16384,K2] @ B2[512,K2]^T --------
// 128x128 tile, BK=32, 256 threads (8 warps, 4x2), m16n8k16 bf16, cp.async double buffer.
// finalmode=0: scatter into (b,h,n,dh) fp32 layout. finalmode=1: C = acc + x + bo.
#define ASTR 40              // padded bf16 per smem row (80B, conflict-free ldmatrix)
#define TILE_B (128 * ASTR)  // bf16 elems per buffer

__global__ __launch_bounds__(256) void k_gemm(const __nv_bfloat16* __restrict__ A,
                                              const __nv_bfloat16* __restrict__ Bw,
                                              float* __restrict__ C,
                                              const float* __restrict__ xres,
                                              const float* __restrict__ bo,
                                              int finalmode) {
    __shared__ __nv_bfloat16 sA[2][TILE_B];
    __shared__ __nv_bfloat16 sB[2][TILE_B];
    int tid = threadIdx.x, lane = tid & 31, w = tid >> 5;
    int m0 = (w & 3) * 32, n0 = (w >> 2) * 64;
    int r0 = blockIdx.x * 128, e0 = blockIdx.y * 128;
    uint32_t sAu = smem_to_u32(sA), sBu = smem_to_u32(sB);

    float acc[2][8][4];
#pragma unroll
    for (int i = 0; i < 2; i++)
#pragma unroll
        for (int j = 0; j < 8; j++)
#pragma unroll
            for (int l = 0; l < 4; l++) acc[i][j][l] = 0.f;

    // loader: each thread owns row tid>>1, 2x16B at col (tid&1)*16 {+0,+8}
    int lrow = tid >> 1;
    int lcol = (tid & 1) << 4;
    const __nv_bfloat16* Arow = A + (size_t)(r0 + lrow) * K2 + lcol;
    const __nv_bfloat16* Brow = Bw + (size_t)(e0 + lrow) * K2 + lcol;
    uint32_t sAdst = sAu + (uint32_t)(lrow * ASTR + lcol) * 2;
    uint32_t sBdst = sBu + (uint32_t)(lrow * ASTR + lcol) * 2;

#define LOAD_TILE(buf, t) do {                                         \
    uint32_t _o = (uint32_t)(buf) * (TILE_B * 2);                      \
    const __nv_bfloat16* _a = Arow + (t) * 32;                         \
    const __nv_bfloat16* _b = Brow + (t) * 32;                         \
    CP_ASYNC16(sAdst + _o,      _a);                                   \
    CP_ASYNC16(sAdst + _o + 16, _a + 8);                               \
    CP_ASYNC16(sBdst + _o,      _b);                                   \
    CP_ASYNC16(sBdst + _o + 16, _b + 8);                               \
} while (0)

    LOAD_TILE(0, 0);
    CP_COMMIT();

    const int NT = K2 / 32;   // 48
#pragma unroll 1
    for (int t = 0; t < NT; ++t) {
        int buf = t & 1;
        if (t + 1 < NT) {
            LOAD_TILE(buf ^ 1, t + 1);
            CP_COMMIT();
            CP_WAIT1();
        } else {
            CP_WAIT0();
        }
        __syncthreads();

        uint32_t ab = sAu + (uint32_t)buf * (TILE_B * 2);
        uint32_t bb = sBu + (uint32_t)buf * (TILE_B * 2);
#pragma unroll
        for (int ks = 0; ks < 32; ks += 16) {
            uint32_t a[2][4];
#pragma unroll
            for (int mt = 0; mt < 2; mt++) {
                uint32_t addr = ab +
                    (uint32_t)((m0 + mt * 16 + (lane & 15)) * ASTR + ks + ((lane >> 4) << 3)) * 2;
                ldm_x4(a[mt][0], a[mt][1], a[mt][2], a[mt][3], addr);
            }
            uint32_t b[8][2];
#pragma unroll
            for (int p = 0; p < 4; p++) {
                int nA = n0 + p * 16;
                uint32_t addr = bb +
                    (uint32_t)((nA + (lane & 7) + ((lane >> 4) << 3)) * ASTR + ks + (lane & 8)) * 2;
                ldm_x4(b[2 * p][0], b[2 * p][1], b[2 * p + 1][0], b[2 * p + 1][1], addr);
            }
#pragma unroll
            for (int mt = 0; mt < 2; mt++)
#pragma unroll
                for (int nt = 0; nt < 8; nt++)
                    mma16816(acc[mt][nt], a[mt], b[nt]);
        }
        __syncthreads();
    }

    // epilogue
    int gid = lane >> 2, tig = lane & 3;
#pragma unroll
    for (int mt = 0; mt < 2; mt++) {
#pragma unroll
        for (int nt = 0; nt < 8; nt++) {
            int r = r0 + m0 + mt * 16 + gid;
            int e = e0 + n0 + nt * 8 + tig * 2;
            float2 v01 = make_float2(acc[mt][nt][0], acc[mt][nt][1]);
            float2 v23 = make_float2(acc[mt][nt][2], acc[mt][nt][3]);
            if (!finalmode) {
                int b = r >> 12, n = r & 4095;
                int h = e >> 6, dh = e & 63;
                float* d0 = C + (((size_t)((b << 3) + h) * Nn + n) * DHd + dh);
                *(float2*)d0 = v01;
                *(float2*)(d0 + 8 * DHd) = v23;   // row r+8, same b/h
            } else {
                size_t b0 = (size_t)r * Dd + e;
                float2 x0 = *(const float2*)(xres + b0);
                float2 x1 = *(const float2*)(xres + b0 + 8 * Dd);
                float2 bv = *(const float2*)(bo + e);
                float2 o0 = make_float2(x0.x + bv.x + v01.x, x0.y + bv.y + v01.y);
                float2 o1 = make_float2(x1.x + bv.x + v23.x, x1.y + bv.y + v23.y);
                *(float2*)(C + b0) = o0;
                *(float2*)(C + b0 + 8 * Dd) = o1;
            }
        }
    }
}

// -------------------- phi_k pass 1: td = (k*nrm)@proj^T, diag, per-head max --------------------
__global__ __launch_bounds__(256) void k_phi_k(const float* __restrict__ proj) {
    __shared__ float Ks[64][68];   // [dh][n]
    __shared__ float Ps[64][68];   // [dh][m]
    __shared__ float red[256];
    int tid = threadIdx.x;
    int n0 = blockIdx.x * 64;
    int m0 = blockIdx.y * 64;
    int bh = blockIdx.z;

#pragma unroll
    for (int i = 0; i < 4; i++) {
        int s = tid + i * 256;
        int row = s >> 4;
        int kc = (s & 15) << 2;
        float4 a = *(const float4*)(g_k + ((size_t)bh * Nn + n0 + row) * DHd + kc);
        Ks[kc + 0][row] = a.x * NORMALIZER; Ks[kc + 1][row] = a.y * NORMALIZER;
        Ks[kc + 2][row] = a.z * NORMALIZER; Ks[kc + 3][row] = a.w * NORMALIZER;
        float4 p = make_float4(0.f, 0.f, 0.f, 0.f);
        if (m0 + row < Mm) p = *(const float4*)(proj + (size_t)(m0 + row) * DHd + kc);
        Ps[kc + 0][row] = p.x; Ps[kc + 1][row] = p.y;
        Ps[kc + 2][row] = p.z; Ps[kc + 3][row] = p.w;
    }
    __syncthreads();

    if (m0 == 0 && tid < 64) {
        float ss = 0.f;
#pragma unroll
        for (int d = 0; d < 64; d++) { float q = Ks[d][tid]; ss += q * q; }
        g_diag[(size_t)bh * Nn + n0 + tid] = 0.5f * ss;
    }

    float acc[4][4];
#pragma unroll
    for (int i = 0; i < 4; i++)
#pragma unroll
        for (int j = 0; j < 4; j++) acc[i][j] = 0.f;
    int ty = tid >> 4, tx = tid & 15;
#pragma unroll
    for (int kk = 0; kk < 64; kk++) {
        float4 a = *(const float4*)&Ks[kk][ty * 4];
        float4 b = *(const float4*)&Ps[kk][tx * 4];
        float ar[4] = {a.x, a.y, a.z, a.w};
        float br[4] = {b.x, b.y, b.z, b.w};
#pragma unroll
        for (int i = 0; i < 4; i++)
#pragma unroll
            for (int j = 0; j < 4; j++) acc[i][j] = fmaf(ar[i], br[j], acc[i][j]);
    }

    float mymax = -3.0e38f;
#pragma unroll
    for (int i = 0; i < 4; i++) {
        int n = n0 + ty * 4 + i;
#pragma unroll
        for (int j = 0; j < 4; j++) {
            int m = m0 + tx * 4 + j;
            if (m < Mm) {
                g_kp[((size_t)bh * Nn + n) * Mm + m] = acc[i][j];
                mymax = fmaxf(mymax, acc[i][j]);
            }
        }
    }
    red[tid] = mymax;
    __syncthreads();
    for (int off = 128; off > 0; off >>= 1) {
        if (tid < off) red[tid] = fmaxf(red[tid], red[tid + off]);
        __syncthreads();
    }
    if (tid == 0) atomicMaxF(&g_kmax[bh], red[0]);
}

// -------------------- phi_k pass 2: exp + column sums --------------------
__global__ __launch_bounds__(256) void k_exp_k() {
    __shared__ float diag_s[64];
    int tid = threadIdx.x;
    int n0 = blockIdx.x * 64;
    int bh = blockIdx.y;
    if (tid < 64) diag_s[tid] = g_diag[(size_t)bh * Nn + n0 + tid];
    __syncthreads();
    float mx = g_kmax[bh];
    for (int m = tid; m < Mm; m += 256) {
        size_t base = ((size_t)bh * Nn + n0) * Mm + m;
        float cs = 0.f;
#pragma unroll 4
        for (int r = 0; r < 64; r++) {
            float td = g_kp[base + (size_t)r * Mm];
            float v = RATIO * (fast_exp(td - diag_s[r] - mx) + EPSF);
            g_kp[base + (size_t)r * Mm] = v;
            cs += v;
        }
        atomicAdd(&g_ksum[bh * Mm + m], cs);
    }
}

// -------------------- phi_q fully fused: td -> rowmax -> exp -> qp + d_inv --------------------
#define QP_SMEM_FLOATS (4352 + 4352 + 17152 + MPAD + 64)
__global__ __launch_bounds__(256) void k_phi_q(const float* __restrict__ proj) {
    extern __shared__ float sm[];
    float* Qs     = sm;                       // 64*68  [dh][n]
    float* Ps     = sm + 4352;                // 64*68  [dh][m]
    float* tds    = sm + 8704;                // 64*MPAD
    float* ksum_s = sm + 8704 + 17152;        // MPAD
    float* diag_s = ksum_s + MPAD;            // 64

    int tid = threadIdx.x;
    int n0 = blockIdx.x * 64;
    int bh = blockIdx.y;

    for (int i = tid; i < Mm; i += 256) ksum_s[i] = g_ksum[bh * Mm + i];

#pragma unroll
    for (int i = 0; i < 4; i++) {
        int s = tid + i * 256;
        int row = s >> 4;
        int kc = (s & 15) << 2;
        float4 a = *(const float4*)(g_q + ((size_t)bh * Nn + n0 + row) * DHd + kc);
        Qs[(kc + 0) * 68 + row] = a.x * NORMALIZER;
        Qs[(kc + 1) * 68 + row] = a.y * NORMALIZER;
        Qs[(kc + 2) * 68 + row] = a.z * NORMALIZER;
        Qs[(kc + 3) * 68 + row] = a.w * NORMALIZER;
    }
    __syncthreads();
    if (tid < 64) {
        float ss = 0.f;
#pragma unroll
        for (int d = 0; d < 64; d++) { float q = Qs[d * 68 + tid]; ss += q * q; }
        diag_s[tid] = 0.5f * ss;
    }

    int ty = tid >> 4, tx = tid & 15;
    for (int mt = 0; mt < 5; mt++) {
        int m0 = mt * 64;
#pragma unroll
        for (int i = 0; i < 4; i++) {
            int s = tid + i * 256;
            int row = s >> 4;
            int kc = (s & 15) << 2;
            float4 p = make_float4(0.f, 0.f, 0.f, 0.f);
            if (m0 + row < Mm) p = *(const float4*)(proj + (size_t)(m0 + row) * DHd + kc);
            Ps[(kc + 0) * 68 + row] = p.x;
            Ps[(kc + 1) * 68 + row] = p.y;
            Ps[(kc + 2) * 68 + row] = p.z;
            Ps[(kc + 3) * 68 + row] = p.w;
        }
        __syncthreads();
        float acc[4][4];
#pragma unroll
        for (int i = 0; i < 4; i++)
#pragma unroll
            for (int j = 0; j < 4; j++) acc[i][j] = 0.f;
#pragma unroll
        for (int kk = 0; kk < 64; kk++) {
            float4 a = *(const float4*)&Qs[kk * 68 + ty * 4];
            float4 b = *(const float4*)&Ps[kk * 68 + tx * 4];
            float ar[4] = {a.x, a.y, a.z, a.w};
            float br[4] = {b.x, b.y, b.z, b.w};
#pragma unroll
            for (int i = 0; i < 4; i++)
#pragma unroll
                for (int j = 0; j < 4; j++) acc[i][j] = fmaf(ar[i], br[j], acc[i][j]);
        }
#pragma unroll
        for (int i = 0; i < 4; i++)
#pragma unroll
            for (int j = 0; j < 4; j++) {
                int m = m0 + tx * 4 + j;
                if (m < Mm) tds[(ty * 4 + i) * MPAD + m] = acc[i][j];
            }
        __syncthreads();
    }

    int row = tid >> 2, lane = tid & 3;
    float pm = -3.0e38f;
    for (int m = lane; m < Mm; m += 4) pm = fmaxf(pm, tds[row * MPAD + m]);
    pm = fmaxf(pm, __shfl_xor_sync(0xffffffffu, pm, 1));
    pm = fmaxf(pm, __shfl_xor_sync(0xffffffffu, pm, 2));
    float dg = diag_s[row];
    float sum = 0.f;
    size_t gb = ((size_t)bh * Nn + n0 + row) * Mm;
    for (int m = lane; m < Mm; m += 4) {
        float v = RATIO * (fast_exp(tds[row * MPAD + m] - dg - pm) + EPSF);
        g_qp[gb + m] = v;
        sum += v * ksum_s[m];
    }
    sum += __shfl_xor_sync(0xffffffffu, sum, 1);
    sum += __shfl_xor_sync(0xffffffffu, sum, 2);
    if (lane == 0) g_dinv[(size_t)bh * Nn + n0 + row] = 1.0f / sum;
}

// -------------------- context: ctx[m,dh] += sum_n kp[n,m]*v[n,dh] (split-K over n) --------------------
__global__ __launch_bounds__(256) void k_ctx() {
    __shared__ float Ksm[64][68];  // [n][m]
    __shared__ float Vs[64][68];   // [n][dh]
    int tid = threadIdx.x;
    int m0 = blockIdx.x * 64;
    int nc = blockIdx.y * 512;
    int bh = blockIdx.z;
    float acc[4][4];
#pragma unroll
    for (int i = 0; i < 4; i++)
#pragma unroll
        for (int j = 0; j < 4; j++) acc[i][j] = 0.f;
    int ty = tid >> 4, tx = tid & 15;

    for (int n0 = nc; n0 < nc + 512; n0 += 64) {
#pragma unroll
        for (int i = 0; i < 16; i++) {
            int s = tid + i * 256;
            int n = s >> 6, mm = s & 63;
            Ksm[n][mm] = (m0 + mm < Mm)
                             ? g_kp[((size_t)bh * Nn + n0 + n) * Mm + m0 + mm]
                             : 0.f;
        }
#pragma unroll
        for (int i = 0; i < 4; i++) {
            int s = tid + i * 256;
            int n = s >> 4, c = (s & 15) << 2;
            float4 v = *(const float4*)(g_v + ((size_t)bh * Nn + n0 + n) * DHd + c);
            Vs[n][c] = v.x; Vs[n][c + 1] = v.y; Vs[n][c + 2] = v.z; Vs[n][c + 3] = v.w;
        }
        __syncthreads();
#pragma unroll
        for (int kk = 0; kk < 64; kk++) {
            float4 a = *(const float4*)&Ksm[kk][ty * 4];
            float4 b = *(const float4*)&Vs[kk][tx * 4];
            float ar[4] = {a.x, a.y, a.z, a.w};
            float br[4] = {b.x, b.y, b.z, b.w};
#pragma unroll
            for (int i = 0; i < 4; i++)
#pragma unroll
                for (int j = 0; j < 4; j++) acc[i][j] = fmaf(ar[i], br[j], acc[i][j]);
        }
        __syncthreads();
    }
#pragma unroll
    for (int i = 0; i < 4; i++) {
        int m = m0 + ty * 4 + i;
        if (m < Mm)
#pragma unroll
            for (int j = 0; j < 4; j++)
                atomicAdd(&g_ctx[((size_t)bh * Mm + m) * DHd + tx * 4 + j], acc[i][j]);
    }
}

// -------------------- out: attn2 (split bf16) = d_inv[n] * sum_m qp[n,m]*ctx[m,dh] --------------------
__global__ __launch_bounds__(256) void k_out() {
    __shared__ float Qs[64][68];  // [k][n]
    __shared__ float Cs[64][68];  // [k][dh]
    int tid = threadIdx.x;
    int n0 = blockIdx.x * 64;
    int bh = blockIdx.y;
    float acc[4][4];
#pragma unroll
    for (int i = 0; i < 4; i++)
#pragma unroll
        for (int j = 0; j < 4; j++) acc[i][j] = 0.f;
    int ty = tid >> 4, tx = tid & 15;

    for (int c0 = 0; c0 < Mm; c0 += 64) {
#pragma unroll
        for (int i = 0; i < 16; i++) {
            int s = tid + i * 256;
            int r = s >> 6, kc = s & 63;
            Qs[kc][r] = (c0 + kc < Mm)
                            ? g_qp[((size_t)bh * Nn + n0 + r) * Mm + c0 + kc]
                            : 0.f;
        }
#pragma unroll
        for (int i = 0; i < 16; i++) {
            int s = tid + i * 256;
            int kk = s >> 6, dh = s & 63;
            Cs[kk][dh] = (c0 + kk < Mm)
                             ? g_ctx[((size_t)bh * Mm + c0 + kk) * DHd + dh]
                             : 0.f;
        }
        __syncthreads();
#pragma unroll
        for (int kk = 0; kk < 64; kk++) {
            float4 a = *(const float4*)&Qs[kk][ty * 4];
            float4 b = *(const float4*)&Cs[kk][tx * 4];
            float ar[4] = {a.x, a.y, a.z, a.w};
            float br[4] = {b.x, b.y, b.z, b.w};
#pragma unroll
            for (int i = 0; i < 4; i++)
#pragma unroll
                for (int j = 0; j < 4; j++) acc[i][j] = fmaf(ar[i], br[j], acc[i][j]);
        }
        __syncthreads();
    }
    int b = bh >> 3, h = bh & 7;
#pragma unroll
    for (int i = 0; i < 4; i++) {
        int n = n0 + ty * 4 + i;
        float dv = g_dinv[(size_t)bh * Nn + n];
        size_t rb = (size_t)(b * Nn + n) * K2 + h * 64 + tx * 4;
#pragma unroll
        for (int j = 0; j < 4; j++) {
            float val = acc[i][j] * dv;
            __nv_bfloat16 hv = __float2bfloat16(val);
            __nv_bfloat16 lv = __float2bfloat16(val - __bfloat162float(hv));
            g_attn2[rb + j]        = hv;   // hi
            g_attn2[rb + 512 + j]  = lv;   // lo  (pairs with Wo hi)
            g_attn2[rb + 1024 + j] = hv;   // hi  (pairs with Wo lo)
        }
    }
}

// -------------------- launch --------------------
extern "C" void kernel_launch(void* const* d_in, const int* in_sizes, int n_in,
                              void* d_out, int out_size) {
    const float* x    = (const float*)d_in[0];
    const float* Wq   = (const float*)d_in[1];
    const float* Wk   = (const float*)d_in[2];
    const float* Wv   = (const float*)d_in[3];
    const float* Wo   = (const float*)d_in[4];
    const float* bo   = (const float*)d_in[5];
    const float* proj = (const float*)d_in[6];
    float* out = (float*)d_out;
    (void)in_sizes; (void)n_in; (void)out_size;

    cudaFuncSetAttribute(k_phi_q, cudaFuncAttributeMaxDynamicSharedMemorySize,
                         QP_SMEM_FLOATS * (int)sizeof(float));

    __nv_bfloat16 *x2p, *wq2p, *wk2p, *wv2p, *wo2p, *attn2p;
    cudaGetSymbolAddress((void**)&x2p, g_x2);
    cudaGetSymbolAddress((void**)&wq2p, g_wq2);
    cudaGetSymbolAddress((void**)&wk2p, g_wk2);
    cudaGetSymbolAddress((void**)&wv2p, g_wv2);
    cudaGetSymbolAddress((void**)&wo2p, g_wo2);
    cudaGetSymbolAddress((void**)&attn2p, g_attn2);
    float *qp_, *kp_, *vp_;
    cudaGetSymbolAddress((void**)&qp_, g_q);
    cudaGetSymbolAddress((void**)&kp_, g_k);
    cudaGetSymbolAddress((void**)&vp_, g_v);

    k_init<<<(BHh * Mm * DHd + 255) / 256, 256>>>();

    // split fp32 -> (hi|lo|hi) / (hi|hi|lo) bf16
    k_split<<<(BNn * 128 + 255) / 256, 256>>>(x, x2p, BNn, 512, 1024);   // A-layout
    k_split<<<(Dd * 128 + 255) / 256, 256>>>(Wq, wq2p, Dd, 1024, 512);   // W-layout
    k_split<<<(Dd * 128 + 255) / 256, 256>>>(Wk, wk2p, Dd, 1024, 512);
    k_split<<<(Dd * 128 + 255) / 256, 256>>>(Wv, wv2p, Dd, 1024, 512);
    k_split<<<(Dd * 128 + 255) / 256, 256>>>(Wo, wo2p, Dd, 1024, 512);

    dim3 gG(BNn / 128, Dd / 128);
    k_gemm<<<gG, 256>>>(x2p, wq2p, qp_, nullptr, nullptr, 0);
    k_gemm<<<gG, 256>>>(x2p, wk2p, kp_, nullptr, nullptr, 0);
    k_gemm<<<gG, 256>>>(x2p, wv2p, vp_, nullptr, nullptr, 0);

    k_phi_k<<<dim3(Nn / 64, 5, BHh), 256>>>(proj);
    k_exp_k<<<dim3(Nn / 64, BHh), 256>>>();
    k_phi_q<<<dim3(Nn / 64, BHh), 256, QP_SMEM_FLOATS * (int)sizeof(float)>>>(proj);

    k_ctx<<<dim3(5, Nn / 512, BHh), 256>>>();
    k_out<<<dim3(Nn / 64, BHh), 256>>>();

    k_gemm<<<gG, 256>>>(attn2p, wo2p, out, x, bo, 1);
}